// round 5
// baseline (speedup 1.0000x reference)
#include <cuda_runtime.h>
#include <math.h>

// ---------------------------------------------------------------------------
// GaussianSceneModel — R5: two-launch pipeline.
//   splat:    per-block param setup in smem; fmaf transforms (bit-exact for
//             identity matrices); exact-IEEE projection; v4/v2 global RED.
//   finalize: streaming scratch->out, 8 cam px/thread, self-cleans scratch
//             (replaces the zero pass; device globals start zeroed).
// ---------------------------------------------------------------------------

#define W_IMG   1600
#define H_IMG   900
#define WL_IMG  1024
#define HL_IMG  128
#define CAM_PIX (W_IMG * H_IMG)          // 1,440,000
#define LID_PIX (WL_IMG * HL_IMG)        // 131,072
#define OFF_RGB   0
#define OFF_DEPTH (3 * CAM_PIX)
#define OFF_ALPHA (4 * CAM_PIX)
#define OFF_LD    (5 * CAM_PIX)
#define OFF_LA    (5 * CAM_PIX + LID_PIX)

#define FMIN_F ((float)(-0.4363323129985824))
#define FMAX_F ((float)(0.05235987755982988))
#define FRANGE_F ((float)(0.05235987755982988 + 0.4363323129985824))
#define TWO_PI_F ((float)(6.283185307179586))
#define SIN_FMIN_LO (-0.42261826f - 1e-4f)
#define SIN_FMAX_HI ( 0.05233596f + 1e-4f)
#define NEAR_PLANE 1.0f
#define FAR_PLANE  100.0f
#define EPS 1e-8f

// Scratch accumulators (device globals: zero-initialized at load; finalize
// re-zeros them each call so every graph replay starts clean).
__device__ float4 g_cam4[CAM_PIX];        // (r*w, g*w, b*w, z*w)
__device__ float4 g_camA4[CAM_PIX / 4];   // sum w (scalar-indexed)
__device__ float2 g_lid2[LID_PIX];        // (r*w, w)

__device__ __forceinline__ void red_add_v4(float4* addr, float a, float b,
                                           float c, float d) {
    asm volatile("red.global.add.v4.f32 [%0], {%1, %2, %3, %4};"
                 :: "l"(addr), "f"(a), "f"(b), "f"(c), "f"(d) : "memory");
}
__device__ __forceinline__ void red_add_v2(float2* addr, float a, float b) {
    asm volatile("red.global.add.v2.f32 [%0], {%1, %2};"
                 :: "l"(addr), "f"(a), "f"(b) : "memory");
}

__device__ void inv4x4(const float* m, float* invOut) {
    float inv[16];
    inv[0] = m[5]*m[10]*m[15] - m[5]*m[11]*m[14] - m[9]*m[6]*m[15] +
             m[9]*m[7]*m[14] + m[13]*m[6]*m[11] - m[13]*m[7]*m[10];
    inv[4] = -m[4]*m[10]*m[15] + m[4]*m[11]*m[14] + m[8]*m[6]*m[15] -
             m[8]*m[7]*m[14] - m[12]*m[6]*m[11] + m[12]*m[7]*m[10];
    inv[8] = m[4]*m[9]*m[15] - m[4]*m[11]*m[13] - m[8]*m[5]*m[15] +
             m[8]*m[7]*m[13] + m[12]*m[5]*m[11] - m[12]*m[7]*m[9];
    inv[12] = -m[4]*m[9]*m[14] + m[4]*m[10]*m[13] + m[8]*m[5]*m[14] -
              m[8]*m[6]*m[13] - m[12]*m[5]*m[10] + m[12]*m[6]*m[9];
    inv[1] = -m[1]*m[10]*m[15] + m[1]*m[11]*m[14] + m[9]*m[2]*m[15] -
             m[9]*m[3]*m[14] - m[13]*m[2]*m[11] + m[13]*m[3]*m[10];
    inv[5] = m[0]*m[10]*m[15] - m[0]*m[11]*m[14] - m[8]*m[2]*m[15] +
             m[8]*m[3]*m[14] + m[12]*m[2]*m[11] - m[12]*m[3]*m[10];
    inv[9] = -m[0]*m[9]*m[15] + m[0]*m[11]*m[13] + m[8]*m[1]*m[15] -
             m[8]*m[3]*m[13] - m[12]*m[1]*m[11] + m[12]*m[3]*m[9];
    inv[13] = m[0]*m[9]*m[14] - m[0]*m[10]*m[13] - m[8]*m[1]*m[14] +
              m[8]*m[2]*m[13] + m[12]*m[1]*m[10] - m[12]*m[2]*m[9];
    inv[2] = m[1]*m[6]*m[15] - m[1]*m[7]*m[14] - m[5]*m[2]*m[15] +
             m[5]*m[3]*m[14] + m[13]*m[2]*m[7] - m[13]*m[3]*m[6];
    inv[6] = -m[0]*m[6]*m[15] + m[0]*m[7]*m[14] + m[4]*m[2]*m[15] -
             m[4]*m[3]*m[14] - m[12]*m[2]*m[7] + m[12]*m[3]*m[6];
    inv[10] = m[0]*m[5]*m[15] - m[0]*m[7]*m[13] - m[4]*m[1]*m[15] +
              m[4]*m[3]*m[13] + m[12]*m[1]*m[7] - m[12]*m[3]*m[5];
    inv[14] = -m[0]*m[5]*m[14] + m[0]*m[6]*m[13] + m[4]*m[1]*m[14] -
              m[4]*m[2]*m[13] - m[12]*m[1]*m[6] + m[12]*m[2]*m[5];
    inv[3] = -m[1]*m[6]*m[11] + m[1]*m[7]*m[10] + m[5]*m[2]*m[11] -
             m[5]*m[3]*m[10] - m[9]*m[2]*m[7] + m[9]*m[3]*m[6];
    inv[7] = m[0]*m[6]*m[11] - m[0]*m[7]*m[10] - m[4]*m[2]*m[11] +
             m[4]*m[3]*m[10] + m[8]*m[2]*m[7] - m[8]*m[3]*m[6];
    inv[11] = -m[0]*m[5]*m[11] + m[0]*m[7]*m[9] + m[4]*m[1]*m[11] -
              m[4]*m[3]*m[9] - m[8]*m[1]*m[7] + m[8]*m[3]*m[5];
    inv[15] = m[0]*m[5]*m[10] - m[0]*m[6]*m[9] - m[4]*m[1]*m[10] +
              m[4]*m[2]*m[9] + m[8]*m[1]*m[6] - m[8]*m[2]*m[5];
    float det = m[0]*inv[0] + m[1]*inv[4] + m[2]*inv[8] + m[3]*inv[12];
    det = 1.0f / det;
    for (int i = 0; i < 16; i++) invOut[i] = inv[i] * det;
}

// fast sigmoid: multiplicative-only error (~1e-7 rel), no 0/nonzero flip.
__device__ __forceinline__ float sigmoid_fast(float x) {
    x = fminf(fmaxf(x, -20.0f), 20.0f);
    return __fdividef(1.0f, 1.0f + __expf(-x));
}

__global__ void __launch_bounds__(256) splat_kernel(
        const float* __restrict__ means,
        const float* __restrict__ sh,
        const float* __restrict__ opa_c,
        const float* __restrict__ opa_l,
        const float* __restrict__ c2w,
        const float* __restrict__ Kmat,
        const float* __restrict__ l2w, int n) {
    __shared__ float sC[12];   // w2c rows 0..2
    __shared__ float sL[12];   // w2l rows 0..2
    __shared__ float sK[4];    // fx, fy, cx, cy
    if (threadIdx.x == 0) {
        float inv[16];
        inv4x4(c2w, inv);
        #pragma unroll
        for (int i = 0; i < 12; i++) sC[i] = inv[i];
        inv4x4(l2w, inv);
        #pragma unroll
        for (int i = 0; i < 12; i++) sL[i] = inv[i];
        sK[0] = Kmat[0]; sK[1] = Kmat[4]; sK[2] = Kmat[2]; sK[3] = Kmat[5];
    }
    __syncthreads();

    int g = blockIdx.x * blockDim.x + threadIdx.x;
    if (g >= n) return;

    const float mx = means[3*g + 0];
    const float my = means[3*g + 1];
    const float mz = means[3*g + 2];

    // ---------------- camera ----------------
    {
        // fmaf chains: bit-exact vs reference when matrix is identity
        float x = fmaf(sC[0], mx, fmaf(sC[1], my, fmaf(sC[2], mz, sC[3])));
        float y = fmaf(sC[4], mx, fmaf(sC[5], my, fmaf(sC[6], mz, sC[7])));
        float z = fmaf(sC[8], mx, fmaf(sC[9], my, fmaf(sC[10], mz, sC[11])));
        if (z > NEAR_PLANE && z < FAR_PLANE) {
            // projection stays exact-IEEE (proven sensitive)
            float u = __fadd_rn(__fdiv_rn(__fmul_rn(sK[0], x), z), sK[2]);
            float v = __fadd_rn(__fdiv_rn(__fmul_rn(sK[1], y), z), sK[3]);
            float u0 = floorf(u), v0 = floorf(v);
            float fu = __fsub_rn(u, u0), fv = __fsub_rn(v, v0);
            int u0i = (int)u0, v0i = (int)v0;
            if (u0i >= -1 && u0i < W_IMG && v0i >= -1 && v0i < H_IMG) {
                float oc = sigmoid_fast(opa_c[g]);
                float cr = sigmoid_fast(sh[48*g + 0]);
                float cg = sigmoid_fast(sh[48*g + 1]);
                float cb = sigmoid_fast(sh[48*g + 2]);
                float ofu = __fsub_rn(1.0f, fu), ofv = __fsub_rn(1.0f, fv);
                float cw[4] = { __fmul_rn(ofu, ofv), __fmul_rn(fu, ofv),
                                __fmul_rn(ofu, fv),  __fmul_rn(fu, fv) };
                #pragma unroll
                for (int c = 0; c < 4; c++) {
                    int ui = u0i + (c & 1);
                    int vi = v0i + (c >> 1);
                    if (ui >= 0 && ui < W_IMG && vi >= 0 && vi < H_IMG) {
                        float ww = __fmul_rn(oc, cw[c]);
                        int pix = vi * W_IMG + ui;
                        red_add_v4(&g_cam4[pix],
                                   __fmul_rn(cr, ww), __fmul_rn(cg, ww),
                                   __fmul_rn(cb, ww), __fmul_rn(z, ww));
                        atomicAdd(&((float*)g_camA4)[pix], ww);
                    }
                }
            }
        }
    }

    // ---------------- lidar ----------------
    {
        float x = fmaf(sL[0], mx, fmaf(sL[1], my, fmaf(sL[2], mz, sL[3])));
        float y = fmaf(sL[4], mx, fmaf(sL[5], my, fmaf(sL[6], mz, sL[7])));
        float z = fmaf(sL[8], mx, fmaf(sL[9], my, fmaf(sL[10], mz, sL[11])));
        // r, s exact (el boundary is a hard include/exclude)
        float r = sqrtf(__fadd_rn(__fadd_rn(__fmul_rn(x,x), __fmul_rn(y,y)), __fmul_rn(z,z)));
        if (r > NEAR_PLANE && r < FAR_PLANE) {
            float s = __fdiv_rn(z, fmaxf(r, 1e-6f));
            if (s >= SIN_FMIN_LO && s <= SIN_FMAX_HI) {
                float el = asinf(s);
                if (el >= FMIN_F && el <= FMAX_F) {
                    float az = atan2f(y, x);
                    float uL = __fmul_rn(__fadd_rn(__fdiv_rn(az, TWO_PI_F), 0.5f), (float)WL_IMG);
                    float vL = __fmul_rn(__fdiv_rn(__fsub_rn(FMAX_F, el), FRANGE_F), (float)(HL_IMG - 1));
                    float u0 = floorf(uL), v0 = floorf(vL);
                    float fu = __fsub_rn(uL, u0), fv = __fsub_rn(vL, v0);
                    int u0i = (int)u0, v0i = (int)v0;
                    float ol = sigmoid_fast(opa_l[g]);
                    float ofu = __fsub_rn(1.0f, fu), ofv = __fsub_rn(1.0f, fv);
                    float cw[4] = { __fmul_rn(ofu, ofv), __fmul_rn(fu, ofv),
                                    __fmul_rn(ofu, fv),  __fmul_rn(fu, fv) };
                    #pragma unroll
                    for (int c = 0; c < 4; c++) {
                        int ui = (u0i + (c & 1)) & (WL_IMG - 1);
                        int vi = v0i + (c >> 1);
                        if (vi >= 0 && vi < HL_IMG) {
                            float ww = __fmul_rn(ol, cw[c]);
                            int pix = vi * WL_IMG + ui;
                            red_add_v2(&g_lid2[pix], __fmul_rn(r, ww), ww);
                        }
                    }
                }
            }
        }
    }
}

__device__ __forceinline__ void stcs4(float4* p, float4 v) {
    __stcs(p, v);
}

// Streaming finalize: 8 camera px/thread, 4 lidar px/thread; self-cleans scratch.
#define CAM_T8 (CAM_PIX / 8)   // 180,000
#define LID_T4 (LID_PIX / 4)   // 32,768
__global__ void __launch_bounds__(256) finalize_kernel(float* __restrict__ out) {
    int t = blockIdx.x * blockDim.x + threadIdx.x;
    const float4 z4 = make_float4(0.f, 0.f, 0.f, 0.f);
    if (t < CAM_T8) {
        float4 acc[8];
        #pragma unroll
        for (int i = 0; i < 8; i++) acc[i] = g_cam4[8*t + i];
        float4 wA = g_camA4[2*t + 0];
        float4 wB = g_camA4[2*t + 1];
        float w[8] = { wA.x, wA.y, wA.z, wA.w, wB.x, wB.y, wB.z, wB.w };
        float rgb[24], d[8], a[8];
        #pragma unroll
        for (int i = 0; i < 8; i++) {
            float wpe = __fadd_rn(w[i], EPS);
            a[i] = fminf(fmaxf(w[i], 0.0f), 1.0f);
            float inv = __fdiv_rn(1.0f, wpe);
            rgb[3*i+0] = __fmul_rn(__fmul_rn(acc[i].x, inv), a[i]);
            rgb[3*i+1] = __fmul_rn(__fmul_rn(acc[i].y, inv), a[i]);
            rgb[3*i+2] = __fmul_rn(__fmul_rn(acc[i].z, inv), a[i]);
            d[i] = __fmul_rn(acc[i].w, inv);
        }
        float4* rgb4 = (float4*)(out + OFF_RGB);
        float4* dep4 = (float4*)(out + OFF_DEPTH);
        float4* alp4 = (float4*)(out + OFF_ALPHA);
        #pragma unroll
        for (int k = 0; k < 6; k++)
            stcs4(&rgb4[6*t + k], make_float4(rgb[4*k+0], rgb[4*k+1],
                                              rgb[4*k+2], rgb[4*k+3]));
        stcs4(&dep4[2*t + 0], make_float4(d[0], d[1], d[2], d[3]));
        stcs4(&dep4[2*t + 1], make_float4(d[4], d[5], d[6], d[7]));
        stcs4(&alp4[2*t + 0], make_float4(a[0], a[1], a[2], a[3]));
        stcs4(&alp4[2*t + 1], make_float4(a[4], a[5], a[6], a[7]));
        // self-clean scratch for the next replay
        #pragma unroll
        for (int i = 0; i < 8; i++) g_cam4[8*t + i] = z4;
        g_camA4[2*t + 0] = z4;
        g_camA4[2*t + 1] = z4;
    } else if (t < CAM_T8 + LID_T4) {
        int j = t - CAM_T8;
        float4 p0 = ((const float4*)g_lid2)[2*j + 0];  // (d0,w0,d1,w1)
        float4 p1 = ((const float4*)g_lid2)[2*j + 1];  // (d2,w2,d3,w3)
        float d[4] = { p0.x, p0.z, p1.x, p1.z };
        float w[4] = { p0.y, p0.w, p1.y, p1.w };
        #pragma unroll
        for (int i = 0; i < 4; i++) {
            d[i] = __fdiv_rn(d[i], __fadd_rn(w[i], EPS));
            w[i] = fminf(fmaxf(w[i], 0.0f), 1.0f);
        }
        float4* ld4 = (float4*)(out + OFF_LD);
        float4* la4 = (float4*)(out + OFF_LA);
        stcs4(&ld4[j], make_float4(d[0], d[1], d[2], d[3]));
        stcs4(&la4[j], make_float4(w[0], w[1], w[2], w[3]));
        ((float4*)g_lid2)[2*j + 0] = z4;
        ((float4*)g_lid2)[2*j + 1] = z4;
    }
}

extern "C" void kernel_launch(void* const* d_in, const int* in_sizes, int n_in,
                              void* d_out, int out_size) {
    const float* means = (const float*)d_in[0];
    const float* sh    = (const float*)d_in[3];
    const float* opa_c = (const float*)d_in[4];
    const float* opa_l = (const float*)d_in[5];
    const float* c2w   = (const float*)d_in[6];
    const float* K     = (const float*)d_in[7];
    const float* l2w   = (const float*)d_in[8];
    float* out = (float*)d_out;

    int n = in_sizes[0] / 3;

    splat_kernel<<<(n + 255) / 256, 256>>>(means, sh, opa_c, opa_l,
                                           c2w, K, l2w, n);
    int tot = CAM_T8 + LID_T4;
    finalize_kernel<<<(tot + 255) / 256, 256>>>(out);
}

// round 6
// speedup vs baseline: 1.1803x; 1.1803x over previous
#include <cuda_runtime.h>
#include <math.h>

// ---------------------------------------------------------------------------
// GaussianSceneModel — R6: three-launch pipeline.
//   zero:     clear scratch (float4 streaming).
//   splat:    4 gaussians/thread (float4 means loads), multiply-form
//             prefilters before all true divisions, v4/v2 global RED.
//   finalize: R4-proven streaming scratch->out, 4 px/thread.
// Exact-IEEE ops kept on everything classification- or weight-critical.
// ---------------------------------------------------------------------------

#define W_IMG   1600
#define H_IMG   900
#define WL_IMG  1024
#define HL_IMG  128
#define CAM_PIX (W_IMG * H_IMG)          // 1,440,000
#define LID_PIX (WL_IMG * HL_IMG)        // 131,072
#define OFF_RGB   0
#define OFF_DEPTH (3 * CAM_PIX)
#define OFF_ALPHA (4 * CAM_PIX)
#define OFF_LD    (5 * CAM_PIX)
#define OFF_LA    (5 * CAM_PIX + LID_PIX)

#define FMIN_F ((float)(-0.4363323129985824))
#define FMAX_F ((float)(0.05235987755982988))
#define FRANGE_F ((float)(0.05235987755982988 + 0.4363323129985824))
#define TWO_PI_F ((float)(6.283185307179586))
#define SIN_FMIN_LO (-0.42261826f - 1e-4f)
#define SIN_FMAX_HI ( 0.05233596f + 1e-4f)
#define NEAR_PLANE 1.0f
#define FAR_PLANE  100.0f
#define EPS 1e-8f

// Scratch accumulators (device globals -- no allocation).
__device__ float4 g_cam4[CAM_PIX];        // (r*w, g*w, b*w, z*w)
__device__ float4 g_camA4[CAM_PIX / 4];   // sum w (scalar-indexed)
__device__ float2 g_lid2[LID_PIX];        // (r*w, w)

__device__ __forceinline__ void red_add_v4(float4* addr, float a, float b,
                                           float c, float d) {
    asm volatile("red.global.add.v4.f32 [%0], {%1, %2, %3, %4};"
                 :: "l"(addr), "f"(a), "f"(b), "f"(c), "f"(d) : "memory");
}
__device__ __forceinline__ void red_add_v2(float2* addr, float a, float b) {
    asm volatile("red.global.add.v2.f32 [%0], {%1, %2};"
                 :: "l"(addr), "f"(a), "f"(b) : "memory");
}

__device__ void inv4x4(const float* m, float* invOut) {
    float inv[16];
    inv[0] = m[5]*m[10]*m[15] - m[5]*m[11]*m[14] - m[9]*m[6]*m[15] +
             m[9]*m[7]*m[14] + m[13]*m[6]*m[11] - m[13]*m[7]*m[10];
    inv[4] = -m[4]*m[10]*m[15] + m[4]*m[11]*m[14] + m[8]*m[6]*m[15] -
             m[8]*m[7]*m[14] - m[12]*m[6]*m[11] + m[12]*m[7]*m[10];
    inv[8] = m[4]*m[9]*m[15] - m[4]*m[11]*m[13] - m[8]*m[5]*m[15] +
             m[8]*m[7]*m[13] + m[12]*m[5]*m[11] - m[12]*m[7]*m[9];
    inv[12] = -m[4]*m[9]*m[14] + m[4]*m[10]*m[13] + m[8]*m[5]*m[14] -
              m[8]*m[6]*m[13] - m[12]*m[5]*m[10] + m[12]*m[6]*m[9];
    inv[1] = -m[1]*m[10]*m[15] + m[1]*m[11]*m[14] + m[9]*m[2]*m[15] -
             m[9]*m[3]*m[14] - m[13]*m[2]*m[11] + m[13]*m[3]*m[10];
    inv[5] = m[0]*m[10]*m[15] - m[0]*m[11]*m[14] - m[8]*m[2]*m[15] +
             m[8]*m[3]*m[14] + m[12]*m[2]*m[11] - m[12]*m[3]*m[10];
    inv[9] = -m[0]*m[9]*m[15] + m[0]*m[11]*m[13] + m[8]*m[1]*m[15] -
             m[8]*m[3]*m[13] - m[12]*m[1]*m[11] + m[12]*m[3]*m[9];
    inv[13] = m[0]*m[9]*m[14] - m[0]*m[10]*m[13] - m[8]*m[1]*m[14] +
              m[8]*m[2]*m[13] + m[12]*m[1]*m[10] - m[12]*m[2]*m[9];
    inv[2] = m[1]*m[6]*m[15] - m[1]*m[7]*m[14] - m[5]*m[2]*m[15] +
             m[5]*m[3]*m[14] + m[13]*m[2]*m[7] - m[13]*m[3]*m[6];
    inv[6] = -m[0]*m[6]*m[15] + m[0]*m[7]*m[14] + m[4]*m[2]*m[15] -
             m[4]*m[3]*m[14] - m[12]*m[2]*m[7] + m[12]*m[3]*m[6];
    inv[10] = m[0]*m[5]*m[15] - m[0]*m[7]*m[13] - m[4]*m[1]*m[15] +
              m[4]*m[3]*m[13] + m[12]*m[1]*m[7] - m[12]*m[3]*m[5];
    inv[14] = -m[0]*m[5]*m[14] + m[0]*m[6]*m[13] + m[4]*m[1]*m[14] -
              m[4]*m[2]*m[13] - m[12]*m[1]*m[6] + m[12]*m[2]*m[5];
    inv[3] = -m[1]*m[6]*m[11] + m[1]*m[7]*m[10] + m[5]*m[2]*m[11] -
             m[5]*m[3]*m[10] - m[9]*m[2]*m[7] + m[9]*m[3]*m[6];
    inv[7] = m[0]*m[6]*m[11] - m[0]*m[7]*m[10] - m[4]*m[2]*m[11] +
             m[4]*m[3]*m[10] + m[8]*m[2]*m[7] - m[8]*m[3]*m[6];
    inv[11] = -m[0]*m[5]*m[11] + m[0]*m[7]*m[9] + m[4]*m[1]*m[11] -
              m[4]*m[3]*m[9] - m[8]*m[1]*m[7] + m[8]*m[3]*m[5];
    inv[15] = m[0]*m[5]*m[10] - m[0]*m[6]*m[9] - m[4]*m[1]*m[10] +
              m[4]*m[2]*m[9] + m[8]*m[1]*m[6] - m[8]*m[2]*m[5];
    float det = m[0]*inv[0] + m[1]*inv[4] + m[2]*inv[8] + m[3]*inv[12];
    det = 1.0f / det;
    for (int i = 0; i < 16; i++) invOut[i] = inv[i] * det;
}

#define Z_CAM4 CAM_PIX
#define Z_CAMA (CAM_PIX / 4)
#define Z_LID  (LID_PIX / 2)
#define Z_TOT  (Z_CAM4 + Z_CAMA + Z_LID)
__global__ void __launch_bounds__(256) zero_kernel() {
    int i = blockIdx.x * blockDim.x + threadIdx.x;
    float4 z = make_float4(0.f, 0.f, 0.f, 0.f);
    if (i < Z_CAM4) {
        g_cam4[i] = z;
    } else if (i < Z_CAM4 + Z_CAMA) {
        g_camA4[i - Z_CAM4] = z;
    } else if (i < Z_TOT) {
        ((float4*)g_lid2)[i - Z_CAM4 - Z_CAMA] = z;
    }
}

__device__ __forceinline__ float sigmoid_fast(float x) {
    x = fminf(fmaxf(x, -20.0f), 20.0f);
    return __fdividef(1.0f, 1.0f + __expf(-x));
}

__device__ __forceinline__ void splat_one(
        float mx, float my, float mz, int g,
        const float* sC, const float* sL, const float* sK,
        const float* __restrict__ sh,
        const float* __restrict__ opa_c,
        const float* __restrict__ opa_l) {
    // ---------------- camera ----------------
    {
        float x = fmaf(sC[0], mx, fmaf(sC[1], my, fmaf(sC[2], mz, sC[3])));
        float y = fmaf(sC[4], mx, fmaf(sC[5], my, fmaf(sC[6], mz, sC[7])));
        float z = fmaf(sC[8], mx, fmaf(sC[9], my, fmaf(sC[10], mz, sC[11])));
        if (z > NEAR_PLANE && z < FAR_PLANE) {
            float tx = __fmul_rn(sK[0], x);   // fx*x (exact; reused for u)
            float ty = __fmul_rn(sK[1], y);
            // multiply-form prefilter (superset of the exact pixel-bound test)
            if (fabsf(tx) < sK[4] * z && fabsf(ty) < sK[5] * z) {
                float u = __fadd_rn(__fdiv_rn(tx, z), sK[2]);
                float v = __fadd_rn(__fdiv_rn(ty, z), sK[3]);
                float u0 = floorf(u), v0 = floorf(v);
                float fu = __fsub_rn(u, u0), fv = __fsub_rn(v, v0);
                int u0i = (int)u0, v0i = (int)v0;
                if (u0i >= -1 && u0i < W_IMG && v0i >= -1 && v0i < H_IMG) {
                    float oc = sigmoid_fast(opa_c[g]);
                    float4 shv = *(const float4*)(sh + 48*g);  // aligned 16B
                    float cr = sigmoid_fast(shv.x);
                    float cg = sigmoid_fast(shv.y);
                    float cb = sigmoid_fast(shv.z);
                    float ofu = __fsub_rn(1.0f, fu), ofv = __fsub_rn(1.0f, fv);
                    float cw[4] = { __fmul_rn(ofu, ofv), __fmul_rn(fu, ofv),
                                    __fmul_rn(ofu, fv),  __fmul_rn(fu, fv) };
                    #pragma unroll
                    for (int c = 0; c < 4; c++) {
                        int ui = u0i + (c & 1);
                        int vi = v0i + (c >> 1);
                        if (ui >= 0 && ui < W_IMG && vi >= 0 && vi < H_IMG) {
                            float ww = __fmul_rn(oc, cw[c]);
                            int pix = vi * W_IMG + ui;
                            red_add_v4(&g_cam4[pix],
                                       __fmul_rn(cr, ww), __fmul_rn(cg, ww),
                                       __fmul_rn(cb, ww), __fmul_rn(z, ww));
                            atomicAdd(&((float*)g_camA4)[pix], ww);
                        }
                    }
                }
            }
        }
    }

    // ---------------- lidar ----------------
    {
        float x = fmaf(sL[0], mx, fmaf(sL[1], my, fmaf(sL[2], mz, sL[3])));
        float y = fmaf(sL[4], mx, fmaf(sL[5], my, fmaf(sL[6], mz, sL[7])));
        float z = fmaf(sL[8], mx, fmaf(sL[9], my, fmaf(sL[10], mz, sL[11])));
        float r = sqrtf(__fadd_rn(__fadd_rn(__fmul_rn(x,x), __fmul_rn(y,y)),
                                  __fmul_rn(z,z)));
        if (r > NEAR_PLANE && r < FAR_PLANE &&
            z >= SIN_FMIN_LO * r && z <= SIN_FMAX_HI * r) {   // mul prefilter
            float s = __fdiv_rn(z, fmaxf(r, 1e-6f));
            float el = asinf(s);
            if (el >= FMIN_F && el <= FMAX_F) {
                float az = atan2f(y, x);
                float uL = __fmul_rn(__fadd_rn(__fdiv_rn(az, TWO_PI_F), 0.5f),
                                     (float)WL_IMG);
                float vL = __fmul_rn(__fdiv_rn(__fsub_rn(FMAX_F, el), FRANGE_F),
                                     (float)(HL_IMG - 1));
                float u0 = floorf(uL), v0 = floorf(vL);
                float fu = __fsub_rn(uL, u0), fv = __fsub_rn(vL, v0);
                int u0i = (int)u0, v0i = (int)v0;
                float ol = sigmoid_fast(opa_l[g]);
                float ofu = __fsub_rn(1.0f, fu), ofv = __fsub_rn(1.0f, fv);
                float cw[4] = { __fmul_rn(ofu, ofv), __fmul_rn(fu, ofv),
                                __fmul_rn(ofu, fv),  __fmul_rn(fu, fv) };
                #pragma unroll
                for (int c = 0; c < 4; c++) {
                    int ui = (u0i + (c & 1)) & (WL_IMG - 1);
                    int vi = v0i + (c >> 1);
                    if (vi >= 0 && vi < HL_IMG) {
                        float ww = __fmul_rn(ol, cw[c]);
                        int pix = vi * WL_IMG + ui;
                        red_add_v2(&g_lid2[pix], __fmul_rn(r, ww), ww);
                    }
                }
            }
        }
    }
}

__global__ void __launch_bounds__(256) splat_kernel(
        const float* __restrict__ means,
        const float* __restrict__ sh,
        const float* __restrict__ opa_c,
        const float* __restrict__ opa_l,
        const float* __restrict__ c2w,
        const float* __restrict__ Kmat,
        const float* __restrict__ l2w, int n) {
    __shared__ float sC[12], sL[12], sK[6];
    if (threadIdx.x == 0) {
        float inv[16];
        inv4x4(c2w, inv);
        #pragma unroll
        for (int i = 0; i < 12; i++) sC[i] = inv[i];
        inv4x4(l2w, inv);
        #pragma unroll
        for (int i = 0; i < 12; i++) sL[i] = inv[i];
        float fx = Kmat[0], fy = Kmat[4], cx = Kmat[2], cy = Kmat[5];
        sK[0] = fx; sK[1] = fy; sK[2] = cx; sK[3] = cy;
        // widened |u-cx|, |v-cy| bounds for the multiply prefilter
        sK[4] = fmaxf(fabsf(-1.0f - cx), fabsf((float)W_IMG + 1.0f - cx)) + 2.0f;
        sK[5] = fmaxf(fabsf(-1.0f - cy), fabsf((float)H_IMG + 1.0f - cy)) + 2.0f;
    }
    __syncthreads();

    int t = blockIdx.x * blockDim.x + threadIdx.x;
    int g0 = 4 * t;
    if (g0 >= n) return;

    if (g0 + 3 < n) {
        const float4* m4 = (const float4*)means;
        float4 A = m4[3*t + 0];
        float4 B = m4[3*t + 1];
        float4 C = m4[3*t + 2];
        float mx[4] = { A.x, A.w, B.z, C.y };
        float my[4] = { A.y, B.x, B.w, C.z };
        float mz[4] = { A.z, B.y, C.x, C.w };
        #pragma unroll
        for (int k = 0; k < 4; k++)
            splat_one(mx[k], my[k], mz[k], g0 + k, sC, sL, sK,
                      sh, opa_c, opa_l);
    } else {
        for (int k = 0; k < 4 && g0 + k < n; k++) {
            int g = g0 + k;
            splat_one(means[3*g], means[3*g+1], means[3*g+2], g, sC, sL, sK,
                      sh, opa_c, opa_l);
        }
    }
}

// Streaming finalize: 4 cam px/thread, 4 lidar px/thread (R4-proven shape).
#define CAM_T (CAM_PIX / 4)   // 360,000
#define LID_T (LID_PIX / 4)   // 32,768
__global__ void __launch_bounds__(256) finalize_kernel(float* __restrict__ out) {
    int t = blockIdx.x * blockDim.x + threadIdx.x;
    if (t < CAM_T) {
        float4 acc[4];
        #pragma unroll
        for (int i = 0; i < 4; i++) acc[i] = g_cam4[4*t + i];
        float4 w4 = g_camA4[t];
        float w[4] = { w4.x, w4.y, w4.z, w4.w };
        float rgb[12], d[4], a[4];
        #pragma unroll
        for (int i = 0; i < 4; i++) {
            float wpe = __fadd_rn(w[i], EPS);
            a[i] = fminf(fmaxf(w[i], 0.0f), 1.0f);
            float inv = __fdiv_rn(1.0f, wpe);
            rgb[3*i+0] = __fmul_rn(__fmul_rn(acc[i].x, inv), a[i]);
            rgb[3*i+1] = __fmul_rn(__fmul_rn(acc[i].y, inv), a[i]);
            rgb[3*i+2] = __fmul_rn(__fmul_rn(acc[i].z, inv), a[i]);
            d[i] = __fmul_rn(acc[i].w, inv);
        }
        float4* rgb4 = (float4*)(out + OFF_RGB);
        float4* dep4 = (float4*)(out + OFF_DEPTH);
        float4* alp4 = (float4*)(out + OFF_ALPHA);
        rgb4[3*t + 0] = make_float4(rgb[0], rgb[1], rgb[2],  rgb[3]);
        rgb4[3*t + 1] = make_float4(rgb[4], rgb[5], rgb[6],  rgb[7]);
        rgb4[3*t + 2] = make_float4(rgb[8], rgb[9], rgb[10], rgb[11]);
        dep4[t] = make_float4(d[0], d[1], d[2], d[3]);
        alp4[t] = make_float4(a[0], a[1], a[2], a[3]);
    } else if (t < CAM_T + LID_T) {
        int j = t - CAM_T;
        float4 p0 = ((const float4*)g_lid2)[2*j + 0];  // (d0,w0,d1,w1)
        float4 p1 = ((const float4*)g_lid2)[2*j + 1];  // (d2,w2,d3,w3)
        float d[4] = { p0.x, p0.z, p1.x, p1.z };
        float w[4] = { p0.y, p0.w, p1.y, p1.w };
        #pragma unroll
        for (int i = 0; i < 4; i++) {
            d[i] = __fdiv_rn(d[i], __fadd_rn(w[i], EPS));
            w[i] = fminf(fmaxf(w[i], 0.0f), 1.0f);
        }
        float4* ld4 = (float4*)(out + OFF_LD);
        float4* la4 = (float4*)(out + OFF_LA);
        ld4[j] = make_float4(d[0], d[1], d[2], d[3]);
        la4[j] = make_float4(w[0], w[1], w[2], w[3]);
    }
}

extern "C" void kernel_launch(void* const* d_in, const int* in_sizes, int n_in,
                              void* d_out, int out_size) {
    const float* means = (const float*)d_in[0];
    const float* sh    = (const float*)d_in[3];
    const float* opa_c = (const float*)d_in[4];
    const float* opa_l = (const float*)d_in[5];
    const float* c2w   = (const float*)d_in[6];
    const float* K     = (const float*)d_in[7];
    const float* l2w   = (const float*)d_in[8];
    float* out = (float*)d_out;

    int n = in_sizes[0] / 3;

    zero_kernel<<<(Z_TOT + 255) / 256, 256>>>();
    int nt = (n + 3) / 4;
    splat_kernel<<<(nt + 255) / 256, 256>>>(means, sh, opa_c, opa_l,
                                            c2w, K, l2w, n);
    int tot = CAM_T + LID_T;
    finalize_kernel<<<(tot + 255) / 256, 256>>>(out);
}